// round 1
// baseline (speedup 1.0000x reference)
#include <cuda_runtime.h>
#include <cstdint>

#define B_ 256
#define T_ 1024
#define D_ 64
#define H_ 100
#define G_ 400   // 4*H

// Scratch for precomputed input-gate contributions: [B, T, 4H] fp32 (~419 MB).
// __device__ global (no cudaMalloc allowed).
__device__ float g_xg[(size_t)B_ * T_ * G_];

// ---------------------------------------------------------------------------
// Packed f32x2 helpers (Blackwell packed FP32 pipe, 2 MACs per FMA issue)
// ---------------------------------------------------------------------------
__device__ __forceinline__ unsigned long long ffma2(unsigned long long a,
                                                    unsigned long long b,
                                                    unsigned long long c) {
    unsigned long long d;
    asm("fma.rn.f32x2 %0, %1, %2, %3;" : "=l"(d) : "l"(a), "l"(b), "l"(c));
    return d;
}
__device__ __forceinline__ unsigned long long pack2(float x, float y) {
    return ((unsigned long long)__float_as_uint(y) << 32) |
           (unsigned long long)__float_as_uint(x);
}
__device__ __forceinline__ float lo2(unsigned long long v) {
    return __uint_as_float((unsigned)v);
}
__device__ __forceinline__ float hi2(unsigned long long v) {
    return __uint_as_float((unsigned)(v >> 32));
}

__device__ __forceinline__ float sig_f(float x) {
    return __fdividef(1.0f, 1.0f + __expf(-x));
}
__device__ __forceinline__ float tanh_f(float x) {
    return 1.0f - __fdividef(2.0f, __expf(2.0f * x) + 1.0f);
}

// ---------------------------------------------------------------------------
// Kernel 1: xg[b,t,g] = sum_k x[b,t,k] * W_ih[g,k] + (b_ih[g]+b_hh[g])
// Grid: (T/64, B). 512 threads; thread g (<400) owns gate row g, W row in regs.
// ---------------------------------------------------------------------------
__global__ __launch_bounds__(512, 1)
void xg_kernel(const float* __restrict__ x,
               const float* __restrict__ W_ih,
               const float* __restrict__ b_ih,
               const float* __restrict__ b_hh) {
    __shared__ ulonglong2 xs[64][16];   // [t][k/4] : 64x64 fp32 tile, 16KB

    const int b   = blockIdx.y;
    const int t0  = blockIdx.x * 64;
    const int tid = threadIdx.x;

    // Load x tile [64 t][64 k] — contiguous 16KB, coalesced float4
    {
        const float4* src = (const float4*)(x + ((size_t)b * T_ + t0) * D_);
        float4* dst = (float4*)xs;
        for (int i = tid; i < 64 * 16; i += 512) dst[i] = src[i];
    }

    unsigned long long w2[32];
    float bias = 0.0f;
    if (tid < G_) {
        const float4* wrow = (const float4*)(W_ih + (size_t)tid * D_);
#pragma unroll
        for (int i = 0; i < 16; i++) {
            float4 v = wrow[i];
            w2[2 * i]     = pack2(v.x, v.y);
            w2[2 * i + 1] = pack2(v.z, v.w);
        }
        bias = b_ih[tid] + b_hh[tid];
    }
    __syncthreads();

    if (tid < G_) {
        float* out = g_xg + ((size_t)b * T_ + t0) * G_ + tid;
#pragma unroll 2
        for (int t = 0; t < 64; t++) {
            unsigned long long a0 = 0ull, a1 = 0ull;
#pragma unroll
            for (int i = 0; i < 16; i++) {
                ulonglong2 xv = xs[t][i];          // broadcast LDS.128
                a0 = ffma2(w2[2 * i],     xv.x, a0);
                a1 = ffma2(w2[2 * i + 1], xv.y, a1);
            }
            out[(size_t)t * G_] =
                (lo2(a0) + hi2(a0)) + (lo2(a1) + hi2(a1)) + bias;
        }
    }
}

// ---------------------------------------------------------------------------
// Kernel 2: recurrence. 128 blocks, each owns 2 batch rows for all T steps.
// Thread g (<400) holds W_hh row g in registers (50 packed f32x2), does the
// gate matvec for both batch rows each step via fma.rn.f32x2 over k-pairs.
// h lives in shared as raw floats, read back as ulonglong2 (f32x2 operands).
// ---------------------------------------------------------------------------
__global__ __launch_bounds__(416, 1)
void lstm_kernel(const float* __restrict__ h0,
                 const float* __restrict__ c0,
                 const float* __restrict__ W_hh,
                 const float* __restrict__ W_fc,
                 const float* __restrict__ b_fc,
                 float* __restrict__ out) {
    __shared__ ulonglong2 hs[2][25];     // 2 x 100 floats (h per batch row)
    __shared__ float gbuf[2][G_];        // activated gates
    __shared__ float wfc_s[H_];

    const int tid    = threadIdx.x;
    const int batch0 = blockIdx.x * 2;

    // Init h, c from h0/c0 (zeros in this problem, but honor inputs)
    float c = 0.0f;
    if (tid < 2 * H_) {
        const int b = tid / H_, j = tid - b * H_;
        ((float*)hs[b])[j] = h0[(size_t)(batch0 + b) * H_ + j];
        c = c0[(size_t)(batch0 + b) * H_ + j];
    }
    if (tid < H_) wfc_s[tid] = W_fc[tid];

    // W_hh row in registers, packed as f32x2 pairs over k
    unsigned long long w2[50];
    if (tid < G_) {
        const float4* wrow = (const float4*)(W_hh + (size_t)tid * H_);
#pragma unroll
        for (int i = 0; i < 25; i++) {
            float4 v = wrow[i];
            w2[2 * i]     = pack2(v.x, v.y);
            w2[2 * i + 1] = pack2(v.z, v.w);
        }
    }

    const float* xg0 = g_xg + (size_t)(batch0)     * T_ * G_ + tid;
    const float* xg1 = g_xg + (size_t)(batch0 + 1) * T_ * G_ + tid;
    float xgc0 = 0.0f, xgc1 = 0.0f;
    if (tid < G_) { xgc0 = xg0[0]; xgc1 = xg1[0]; }

    __syncthreads();

    for (int t = 0; t < T_; t++) {
        // Prefetch next step's xg (hidden behind the matvec)
        float xgn0 = 0.0f, xgn1 = 0.0f;
        if (tid < G_ && t + 1 < T_) {
            xgn0 = xg0[(size_t)(t + 1) * G_];
            xgn1 = xg1[(size_t)(t + 1) * G_];
        }

        if (tid < G_) {
            unsigned long long a0 = 0ull, a1 = 0ull, b0 = 0ull, b1 = 0ull;
#pragma unroll
            for (int i = 0; i < 25; i++) {
                ulonglong2 hv = hs[0][i];          // broadcast LDS.128
                a0 = ffma2(w2[2 * i],     hv.x, a0);
                a1 = ffma2(w2[2 * i + 1], hv.y, a1);
            }
#pragma unroll
            for (int i = 0; i < 25; i++) {
                ulonglong2 hv = hs[1][i];
                b0 = ffma2(w2[2 * i],     hv.x, b0);
                b1 = ffma2(w2[2 * i + 1], hv.y, b1);
            }
            float acc0 = lo2(a0) + hi2(a0) + lo2(a1) + hi2(a1) + xgc0;
            float acc1 = lo2(b0) + hi2(b0) + lo2(b1) + hi2(b1) + xgc1;

            float r0, r1;
            if (tid >= 200 && tid < 300) {         // cell gate g -> tanh
                r0 = tanh_f(acc0);
                r1 = tanh_f(acc1);
            } else {                               // i, f, o -> sigmoid
                r0 = sig_f(acc0);
                r1 = sig_f(acc1);
            }
            gbuf[0][tid] = r0;
            gbuf[1][tid] = r1;
        }
        __syncthreads();

        if (tid < 2 * H_) {
            const int b = tid / H_, j = tid - b * H_;
            float iv = gbuf[b][j];
            float fv = gbuf[b][H_ + j];
            float gv = gbuf[b][2 * H_ + j];
            float ov = gbuf[b][3 * H_ + j];
            c = fv * c + iv * gv;
            ((float*)hs[b])[j] = ov * tanh_f(c);
        }
        xgc0 = xgn0;
        xgc1 = xgn1;
        __syncthreads();
    }

    // FC head on final hidden state: out[b] = h_T . W_fc + b_fc
    if (tid < 2) {
        float acc = b_fc[0];
        const float* hp = (const float*)hs[tid];
#pragma unroll 4
        for (int j = 0; j < H_; j++) acc += hp[j] * wfc_s[j];
        out[batch0 + tid] = acc;
    }
}

// ---------------------------------------------------------------------------
extern "C" void kernel_launch(void* const* d_in, const int* in_sizes, int n_in,
                              void* d_out, int out_size) {
    const float* x    = (const float*)d_in[0];
    const float* h0   = (const float*)d_in[1];
    const float* c0   = (const float*)d_in[2];
    const float* W_ih = (const float*)d_in[3];
    const float* W_hh = (const float*)d_in[4];
    const float* b_ih = (const float*)d_in[5];
    const float* b_hh = (const float*)d_in[6];
    const float* W_fc = (const float*)d_in[7];
    const float* b_fc = (const float*)d_in[8];
    float* out = (float*)d_out;

    dim3 grid1(T_ / 64, B_);
    xg_kernel<<<grid1, 512>>>(x, W_ih, b_ih, b_hh);

    lstm_kernel<<<B_ / 2, 416>>>(h0, c0, W_hh, W_fc, b_fc, out);
}